// round 12
// baseline (speedup 1.0000x reference)
#include <cuda_runtime.h>
#include <math.h>
#include <stdint.h>

#define V_N 100000
#define D_N 300
#define K_N 200
#define B_N 256
#define OUTSTRIDE (K_N + V_N)

typedef unsigned long long u64;

// ---------------- f32x2 packed-math helpers ----------------
__device__ __forceinline__ u64 pack2(float lo, float hi) {
    u64 r;
    asm("mov.b64 %0, {%1, %2};" : "=l"(r)
        : "r"(__float_as_uint(lo)), "r"(__float_as_uint(hi)));
    return r;
}
__device__ __forceinline__ void unpack2(u64 v, float& lo, float& hi) {
    unsigned a, b;
    asm("mov.b64 {%0, %1}, %2;" : "=r"(a), "=r"(b) : "l"(v));
    lo = __uint_as_float(a);
    hi = __uint_as_float(b);
}
__device__ __forceinline__ u64 fma2(u64 a, u64 b, u64 c) {
    u64 d;
    asm("fma.rn.f32x2 %0, %1, %2, %3;" : "=l"(d) : "l"(a), "l"(b), "l"(c));
    return d;
}

// ---------------- scratch (static device globals; no runtime alloc) ----------------
#define DP (D_N / 2)                            // 150 d-pairs
__device__ float g_logp[(size_t)K_N * V_N];     // 80 MB, layout [K][V]
// interleaved per (d-pair, k): {dinv_lo, dinv_hi, -2mdi_lo, -2mdi_hi}
__device__ float g_dmP[DP * K_N * 4];
// per (d-pair, k): {u_lo, u_hi}
__device__ float g_uP2[DP * K_N * 2];
__device__ float g_c1[K_N], g_c2[K_N], g_capinv[K_N], g_constk[K_N];
__device__ float g_softc[K_N];                  // m_k + log(S_k)
__device__ float g_pmax[K_N * 8];               // per-chunk max
__device__ float g_psum[K_N * 8];               // per-chunk sum (local-max referenced)
__device__ float g_sxT[K_N * B_N];              // sampled_x transposed [K][B]

// ---------------- kernel 1: per-topic precompute ----------------
__global__ void topic_prep(const float* __restrict__ mu,
                           const float* __restrict__ cf,
                           const float* __restrict__ cd) {
    int k = blockIdx.x;
    int tid = threadIdx.x;
    float capa = 0.f, ld = 0.f, c1 = 0.f, c2 = 0.f;
    for (int d = tid; d < D_N; d += blockDim.x) {
        float diag = cd[k * D_N + d];
        float dinv = 1.0f / diag;
        float m    = mu[k * D_N + d];
        float w    = cf[k * D_N + d];
        float u    = w * dinv;
        float mdi  = m * dinv;
        int dp = d >> 1, h = d & 1;
        g_dmP[dp * (K_N * 4) + k * 4 + h]     = dinv;
        g_dmP[dp * (K_N * 4) + k * 4 + 2 + h] = -2.0f * mdi;
        g_uP2[dp * (K_N * 2) + k * 2 + h]     = u;
        capa += w * u;
        ld   += logf(diag);
        c1   += m * mdi;
        c2   += m * u;
    }
    __shared__ float s[4][128];
    s[0][tid] = capa; s[1][tid] = ld; s[2][tid] = c1; s[3][tid] = c2;
    __syncthreads();
    for (int off = 64; off > 0; off >>= 1) {
        if (tid < off) {
            s[0][tid] += s[0][tid + off];
            s[1][tid] += s[1][tid + off];
            s[2][tid] += s[2][tid + off];
            s[3][tid] += s[3][tid + off];
        }
        __syncthreads();
    }
    if (tid == 0) {
        float cap    = 1.0f + s[0][0];
        float logdet = s[1][0] + logf(cap);
        g_c1[k]     = s[2][0];
        g_c2[k]     = s[3][0];
        g_capinv[k] = 1.0f / cap;
        const float LOG2PI = 1.8378770664093453f;
        g_constk[k] = -0.5f * ((float)D_N * LOG2PI + logdet);
    }
}

// ---------------- kernel 2: copy sampled_x into out[:, :K] + transpose ----------------
__global__ void sx_prep(const float* __restrict__ sx, float* __restrict__ out) {
    int idx = blockIdx.x * blockDim.x + threadIdx.x;
    if (idx < B_N * K_N) {
        int b = idx / K_N, k = idx % K_N;
        float v = sx[idx];
        out[(size_t)b * OUTSTRIDE + k] = v;
        g_sxT[k * B_N + b] = v;
    }
}

// ---------------- kernel 3: logp (V x K), f32x2 + double-buffered prefetch ----------------
#define MV 256
#define NK 40
#define SDM (DP * NK * 4)                        // 24000 floats
#define SU  (DP * NK * 2)                        // 12000 floats
#define SMEM_LOGP ((SDM + SU) * sizeof(float))   // 144 KB

__global__ __launch_bounds__(512, 1) void logp_kernel(const float* __restrict__ wv) {
    extern __shared__ float smem[];
    float* s_dm = smem;          // [DP][NK][4] : dinv pair + (-2mdi) pair
    float* s_u  = smem + SDM;    // [DP][NK][2] : u pair

    const int k0 = blockIdx.x * NK;  // k fastest in grid -> L2 reuse of word rows
    const int v0 = blockIdx.y * MV;
    const int tid = threadIdx.x;

    for (int e = tid; e < SDM; e += 512) {
        int dp = e / (NK * 4);
        int r  = e - dp * (NK * 4);
        s_dm[e] = g_dmP[dp * (K_N * 4) + k0 * 4 + r];
    }
    for (int e = tid; e < SU; e += 512) {
        int dp = e / (NK * 2);
        int r  = e - dp * (NK * 2);
        s_u[e] = g_uP2[dp * (K_N * 2) + k0 * 2 + r];
    }
    __syncthreads();

    const int tv = tid & 63;   // 0..63 word group (x4 rows = 256 words per block)
    const int tk = tid >> 6;   // 0..7 topic group (uniform per warp -> smem broadcast)
    const int kb = tk * 5;
    const float* dmbase = s_dm + kb * 4;
    const float* ubase  = s_u  + kb * 2;

    u64 accqm[4][5], accu[4][5];
#pragma unroll
    for (int i = 0; i < 4; i++)
#pragma unroll
        for (int j = 0; j < 5; j++) { accqm[i][j] = 0ull; accu[i][j] = 0ull; }

    const int vbase = v0 + tv * 4;   // multiple of 4; V_N % 4 == 0
    const bool vvalid = (vbase < V_N);
    const float* wrow = wv + (size_t)vbase * D_N;

    float4 bufA[4], bufB[4];

    auto LD = [&](float4* buf, int d0) {
#pragma unroll
        for (int i = 0; i < 4; i++)
            buf[i] = vvalid
                ? *reinterpret_cast<const float4*>(wrow + (size_t)i * D_N + d0)
                : make_float4(0.f, 0.f, 0.f, 0.f);
    };
    auto COMP = [&](const float4* buf, int d0) {
#pragma unroll
        for (int h = 0; h < 2; h++) {
            const int dp = (d0 >> 1) + h;
            u64 wpk[4];
#pragma unroll
            for (int i = 0; i < 4; i++)
                wpk[i] = h ? pack2(buf[i].z, buf[i].w) : pack2(buf[i].x, buf[i].y);
            const float4* pdm = reinterpret_cast<const float4*>(dmbase + dp * (NK * 4));
            const u64*    pu  = reinterpret_cast<const u64*>   (ubase  + dp * (NK * 2));
#pragma unroll
            for (int j = 0; j < 5; j++) {
                float4 dm = pdm[j];
                u64 dv = pack2(dm.x, dm.y);
                u64 mm = pack2(dm.z, dm.w);
                u64 uu = pu[j];
#pragma unroll
                for (int i = 0; i < 4; i++) {
                    u64 inner = fma2(wpk[i], dv, mm);              // w*dinv - 2*mdi
                    accqm[i][j] = fma2(wpk[i], inner, accqm[i][j]); // += w^2*dinv - 2*w*mdi
                    accu[i][j]  = fma2(wpk[i], uu, accu[i][j]);     // += w*u
                }
            }
        }
    };

    // software pipeline: 75 d0-steps = 37 double-steps + 1 peel
    LD(bufA, 0);
    int d0 = 0;
#pragma unroll 1
    for (int it = 0; it < 37; it++) {
        LD(bufB, d0 + 4);
        COMP(bufA, d0);
        LD(bufA, d0 + 8);
        COMP(bufB, d0 + 4);
        d0 += 8;
    }
    COMP(bufA, 296);   // last step (d 296..299)

    if (vvalid) {
#pragma unroll
        for (int j = 0; j < 5; j++) {
            int k = k0 + kb + j;
            float c1 = g_c1[k], c2 = g_c2[k], ci = g_capinv[k], ck = g_constk[k];
            float r[4];
#pragma unroll
            for (int i = 0; i < 4; i++) {
                float qa, qb, ta, tb;
                unpack2(accqm[i][j], qa, qb);
                unpack2(accu[i][j], ta, tb);
                float q = qa + qb + c1;
                float t = ta + tb - c2;
                r[i] = ck - 0.5f * (q - t * t * ci);
            }
            *reinterpret_cast<float4*>(&g_logp[(size_t)k * V_N + vbase]) =
                make_float4(r[0], r[1], r[2], r[3]);
        }
    }
}

// ---------------- kernel 4a: per-(topic, chunk) partial max/sum ----------------
#define NCH 8
#define CHV (V_N / NCH)   // 12500, divisible by 4

__global__ void softmax_partial() {
    const int k = blockIdx.x;
    const int c = blockIdx.y;
    const int tid = threadIdx.x;
    const float4* p = reinterpret_cast<const float4*>(&g_logp[(size_t)k * V_N + c * CHV]);
    const int n4 = CHV / 4;

    float m = -3.4e38f;
    for (int f = tid; f < n4; f += 256) {
        float4 x = p[f];
        m = fmaxf(m, fmaxf(fmaxf(x.x, x.y), fmaxf(x.z, x.w)));
    }
    __shared__ float red[256];
    red[tid] = m;
    __syncthreads();
    for (int off = 128; off > 0; off >>= 1) {
        if (tid < off) red[tid] = fmaxf(red[tid], red[tid + off]);
        __syncthreads();
    }
    float M = red[0];
    __syncthreads();

    float s = 0.f;
    for (int f = tid; f < n4; f += 256) {
        float4 x = p[f];
        s += __expf(x.x - M) + __expf(x.y - M) + __expf(x.z - M) + __expf(x.w - M);
    }
    red[tid] = s;
    __syncthreads();
    for (int off = 128; off > 0; off >>= 1) {
        if (tid < off) red[tid] += red[tid + off];
        __syncthreads();
    }
    if (tid == 0) {
        g_pmax[k * NCH + c] = M;
        g_psum[k * NCH + c] = red[0];
    }
}

// ---------------- kernel 4b: merge partials -> g_softc ----------------
__global__ void softmax_merge() {
    int k = blockIdx.x * blockDim.x + threadIdx.x;
    if (k < K_N) {
        float M = -3.4e38f;
#pragma unroll
        for (int c = 0; c < NCH; c++) M = fmaxf(M, g_pmax[k * NCH + c]);
        float S = 0.f;
#pragma unroll
        for (int c = 0; c < NCH; c++)
            S += g_psum[k * NCH + c] * __expf(g_pmax[k * NCH + c] - M);
        g_softc[k] = M + logf(S);
    }
}

// ---------------- kernel 5: word_dist = sx @ softmax(logp), f32x2 over v ----------------
#define VT 64
#define BT 64
#define KC 8

__global__ __launch_bounds__(256) void out_gemm(float* __restrict__ out) {
    __shared__ float wt [KC][VT];   // exp-normalized P tile
    __shared__ float sxs[KC][BT];

    // b-dim is grid.x (fastest) so the 4 blocks sharing a logp tile are
    // schedule-adjacent -> L2 reuse of g_logp
    const int b0 = blockIdx.x * BT;
    const int v0 = blockIdx.y * VT;
    const int tid = threadIdx.x;
    const int tv = tid & 15;        // 16 v-groups of 4
    const int tb = tid >> 4;        // 16 b-groups of 4

    u64 acc[4][2];                  // [jb][v-pair]
#pragma unroll
    for (int a = 0; a < 4; a++) { acc[a][0] = 0ull; acc[a][1] = 0ull; }

    for (int kc = 0; kc < K_N; kc += KC) {
        __syncthreads();
#pragma unroll
        for (int r = 0; r < 2; r++) {
            int e = tid + r * 256;
            int kk = e >> 6, vv = e & 63;
            int k = kc + kk;
            int v = v0 + vv;
            float x = (v < V_N) ? g_logp[(size_t)k * V_N + v] : -3.0e38f;
            wt[kk][vv] = __expf(x - g_softc[k]);   // normalized probability
        }
#pragma unroll
        for (int r = 0; r < 2; r++) {
            int e = tid + r * 256;
            int kk = e >> 6, bb = e & 63;
            sxs[kk][bb] = g_sxT[(kc + kk) * B_N + b0 + bb];
        }
        __syncthreads();
#pragma unroll
        for (int kk = 0; kk < KC; kk++) {
            const u64* ap = reinterpret_cast<const u64*>(&wt[kk][tv * 4]);
            u64 a0 = ap[0], a1 = ap[1];
            float4 s4 = *reinterpret_cast<const float4*>(&sxs[kk][tb * 4]);
            u64 sd0 = pack2(s4.x, s4.x);
            u64 sd1 = pack2(s4.y, s4.y);
            u64 sd2 = pack2(s4.z, s4.z);
            u64 sd3 = pack2(s4.w, s4.w);
            acc[0][0] = fma2(sd0, a0, acc[0][0]); acc[0][1] = fma2(sd0, a1, acc[0][1]);
            acc[1][0] = fma2(sd1, a0, acc[1][0]); acc[1][1] = fma2(sd1, a1, acc[1][1]);
            acc[2][0] = fma2(sd2, a0, acc[2][0]); acc[2][1] = fma2(sd2, a1, acc[2][1]);
            acc[3][0] = fma2(sd3, a0, acc[3][0]); acc[3][1] = fma2(sd3, a1, acc[3][1]);
        }
    }

    const int vw = v0 + tv * 4;
    if (vw < V_N) {
#pragma unroll
        for (int jb = 0; jb < 4; jb++) {
            int b = b0 + tb * 4 + jb;
            float r0, r1, r2, r3;
            unpack2(acc[jb][0], r0, r1);
            unpack2(acc[jb][1], r2, r3);
            *reinterpret_cast<float4*>(&out[(size_t)b * OUTSTRIDE + K_N + vw]) =
                make_float4(r0, r1, r2, r3);
        }
    }
}

// ---------------- launch ----------------
extern "C" void kernel_launch(void* const* d_in, const int* in_sizes, int n_in,
                              void* d_out, int out_size) {
    const float* sx = (const float*)d_in[0];   // (256, 200)
    const float* wv = (const float*)d_in[1];   // (100000, 300)
    const float* mu = (const float*)d_in[2];   // (200, 300)
    const float* cf = (const float*)d_in[3];   // (200, 300)
    const float* cd = (const float*)d_in[4];   // (200, 300)
    float* out = (float*)d_out;                // (256, 100200)

    cudaFuncSetAttribute(logp_kernel, cudaFuncAttributeMaxDynamicSharedMemorySize,
                         (int)SMEM_LOGP);

    topic_prep<<<K_N, 128>>>(mu, cf, cd);
    sx_prep<<<(B_N * K_N + 255) / 256, 256>>>(sx, out);
    logp_kernel<<<dim3(K_N / NK, (V_N + MV - 1) / MV), 512, SMEM_LOGP>>>(wv);
    softmax_partial<<<dim3(K_N, NCH), 256>>>();
    softmax_merge<<<1, 256>>>();
    out_gemm<<<dim3(B_N / BT, (V_N + VT - 1) / VT), 256>>>(out);
}

// round 14
// speedup vs baseline: 1.5008x; 1.5008x over previous
#include <cuda_runtime.h>
#include <cuda_bf16.h>
#include <math.h>
#include <stdint.h>

#define V_N 100000
#define D_N 300
#define K_N 200
#define B_N 256
#define OUTSTRIDE (K_N + V_N)

#define VTILES 1563
#define VPAD (VTILES * 64)        // 100032

typedef unsigned long long u64;
typedef unsigned int u32;

// ---------------- f32x2 packed helpers (for out_gemm) ----------------
__device__ __forceinline__ u64 pack2(float lo, float hi) {
    u64 r;
    asm("mov.b64 %0, {%1, %2};" : "=l"(r)
        : "r"(__float_as_uint(lo)), "r"(__float_as_uint(hi)));
    return r;
}
__device__ __forceinline__ void unpack2(u64 v, float& lo, float& hi) {
    u32 a, b;
    asm("mov.b64 {%0, %1}, %2;" : "=r"(a), "=r"(b) : "l"(v));
    lo = __uint_as_float(a);
    hi = __uint_as_float(b);
}
__device__ __forceinline__ u64 fma2(u64 a, u64 b, u64 c) {
    u64 d;
    asm("fma.rn.f32x2 %0, %1, %2, %3;" : "=l"(d) : "l"(a), "l"(b), "l"(c));
    return d;
}

// ---------------- warp mma.sync bf16 ----------------
__device__ __forceinline__ void mma16816(float* d, const u32* a, const u32* b) {
    asm volatile(
        "mma.sync.aligned.m16n8k16.row.col.f32.bf16.bf16.f32 "
        "{%0,%1,%2,%3}, {%4,%5,%6,%7}, {%8,%9}, {%0,%1,%2,%3};"
        : "+f"(d[0]), "+f"(d[1]), "+f"(d[2]), "+f"(d[3])
        : "r"(a[0]), "r"(a[1]), "r"(a[2]), "r"(a[3]), "r"(b[0]), "r"(b[1]));
}

// ---------------- scratch (static device globals; BSS zero-init) ----------------
__device__ float g_logp[(size_t)K_N * V_N];                 // 80 MB [K][V]
// A operands, 256 k-rows. Aqm cols [0,1280): [dinv_h(320)|m2_h(320)|dinv_l(320)|m2_l(320)]
__device__ __nv_bfloat16 g_Aqm[256 * 1280];
// At cols [0,640): [u_h(320)|u_l(320)]
__device__ __nv_bfloat16 g_At[256 * 640];
// B operand [VPAD][1280]: [w2_h(320)|w_h(320)|w2_l(320)|w_l(320)]
__device__ __nv_bfloat16 g_Bx[(size_t)VPAD * 1280];
__device__ float g_c1[K_N], g_c2[K_N], g_capinv[K_N], g_constk[K_N];
__device__ float g_softc[K_N];
__device__ float g_pmax[K_N * 8];
__device__ float g_psum[K_N * 8];
__device__ float g_sxT[K_N * B_N];

__device__ __forceinline__ void bsplit(float x, __nv_bfloat16& hi, __nv_bfloat16& lo) {
    hi = __float2bfloat16(x);
    lo = __float2bfloat16(x - __bfloat162float(hi));
}

// ---------------- kernel 1: per-topic precompute + A operand split ----------------
__global__ void topic_prep(const float* __restrict__ mu,
                           const float* __restrict__ cf,
                           const float* __restrict__ cd) {
    int k = blockIdx.x;
    int tid = threadIdx.x;
    float capa = 0.f, ld = 0.f, c1 = 0.f, c2 = 0.f;
    for (int d = tid; d < D_N; d += blockDim.x) {
        float diag = cd[k * D_N + d];
        float dinv = 1.0f / diag;
        float m    = mu[k * D_N + d];
        float w    = cf[k * D_N + d];
        float u    = w * dinv;
        float mdi  = m * dinv;
        float m2   = -2.0f * mdi;
        __nv_bfloat16 hi, lo;
        bsplit(dinv, hi, lo);
        g_Aqm[k * 1280 + d]        = hi;
        g_Aqm[k * 1280 + 640 + d]  = lo;
        bsplit(m2, hi, lo);
        g_Aqm[k * 1280 + 320 + d]  = hi;
        g_Aqm[k * 1280 + 960 + d]  = lo;
        bsplit(u, hi, lo);
        g_At[k * 640 + d]          = hi;
        g_At[k * 640 + 320 + d]    = lo;
        capa += w * u;
        ld   += logf(diag);
        c1   += m * mdi;
        c2   += m * u;
    }
    __shared__ float s[4][128];
    s[0][tid] = capa; s[1][tid] = ld; s[2][tid] = c1; s[3][tid] = c2;
    __syncthreads();
    for (int off = 64; off > 0; off >>= 1) {
        if (tid < off) {
            s[0][tid] += s[0][tid + off];
            s[1][tid] += s[1][tid + off];
            s[2][tid] += s[2][tid + off];
            s[3][tid] += s[3][tid + off];
        }
        __syncthreads();
    }
    if (tid == 0) {
        float cap    = 1.0f + s[0][0];
        float logdet = s[1][0] + logf(cap);
        g_c1[k]     = s[2][0];
        g_c2[k]     = s[3][0];
        g_capinv[k] = 1.0f / cap;
        const float LOG2PI = 1.8378770664093453f;
        g_constk[k] = -0.5f * ((float)D_N * LOG2PI + logdet);
    }
}

// ---------------- kernel 1b: word-vector bf16 hi/lo split (+ squares) ----------------
// thread handles 8 consecutive d of one word row; writes 4 sections as uint4
__global__ void wsplit(const float* __restrict__ wv) {
    int idx = blockIdx.x * blockDim.x + threadIdx.x;
    if (idx >= V_N * 40) return;
    int v    = idx / 40;
    int dblk = idx - v * 40;
    int d0   = dblk * 8;

    __align__(16) __nv_bfloat16 wh[8], wl[8], w2h[8], w2l[8];
#pragma unroll
    for (int e = 0; e < 8; e++) {
        int d = d0 + e;
        float w = (d < D_N) ? wv[(size_t)v * D_N + d] : 0.f;
        float w2 = w * w;
        bsplit(w, wh[e], wl[e]);
        bsplit(w2, w2h[e], w2l[e]);
    }
    size_t base = (size_t)v * 1280 + d0;
    *reinterpret_cast<uint4*>(&g_Bx[base])        = *reinterpret_cast<uint4*>(w2h);
    *reinterpret_cast<uint4*>(&g_Bx[base + 320])  = *reinterpret_cast<uint4*>(wh);
    *reinterpret_cast<uint4*>(&g_Bx[base + 640])  = *reinterpret_cast<uint4*>(w2l);
    *reinterpret_cast<uint4*>(&g_Bx[base + 960])  = *reinterpret_cast<uint4*>(wl);
}

// ---------------- kernel 2: copy sampled_x into out[:, :K] + transpose ----------------
__global__ void sx_prep(const float* __restrict__ sx, float* __restrict__ out) {
    int idx = blockIdx.x * blockDim.x + threadIdx.x;
    if (idx < B_N * K_N) {
        int b = idx / K_N, k = idx % K_N;
        float v = sx[idx];
        out[(size_t)b * OUTSTRIDE + k] = v;
        g_sxT[k * B_N + b] = v;
    }
}

// ---------------- kernel 3: logp via mma.sync bf16 split-GEMM ----------------
// CTA: 128 k x 64 v, 8 warps (warp tile 32x32). 90 chunks of k=32 contraction.
#define SAPAD 40                   // smem row stride (elements), conflict-free

__global__ __launch_bounds__(256, 2) void logp_mma() {
    __shared__ __nv_bfloat16 sA[2][128 * SAPAD];
    __shared__ __nv_bfloat16 sB[2][64 * SAPAD];

    const int tid = threadIdx.x;
    const int wid = tid >> 5;
    const int lid = tid & 31;
    const int g   = lid >> 2;      // group 0..7
    const int t   = lid & 3;       // 0..3
    const int warp_m = wid & 3;    // 0..3  -> k rows warp_m*32
    const int warp_n = wid >> 2;   // 0..1  -> v cols warp_n*32

    const int k0 = blockIdx.x * 128;
    const int v0 = blockIdx.y * 64;

    float accQ[2][4][4], accT[2][4][4];
#pragma unroll
    for (int mf = 0; mf < 2; mf++)
#pragma unroll
        for (int nf = 0; nf < 4; nf++)
#pragma unroll
            for (int e = 0; e < 4; e++) { accQ[mf][nf][e] = 0.f; accT[mf][nf][e] = 0.f; }

    // chunk schedule: c<60 -> qm (3 passes x 20 chunks); else t (3 x 10)
    auto sched = [&](int c, const __nv_bfloat16*& Abase, int& astride,
                     int& Acol, int& Bcol) {
        if (c < 60) {
            int p = c / 20, cc = c - p * 20;
            Abase = g_Aqm; astride = 1280;
            Acol = ((p == 2) ? 640 : 0) + cc * 32;
            Bcol = ((p == 1) ? 640 : 0) + cc * 32;
        } else {
            int c2 = c - 60;
            int p = c2 / 10, cc = c2 - p * 10;
            Abase = g_At; astride = 640;
            Acol = ((p == 2) ? 320 : 0) + cc * 32;
            Bcol = ((p == 1) ? 960 : 320) + cc * 32;
        }
    };

    uint4 ra[2], rb;
    auto load = [&](int c) {
        const __nv_bfloat16* Abase; int astride, Acol, Bcol;
        sched(c, Abase, astride, Acol, Bcol);
#pragma unroll
        for (int r = 0; r < 2; r++) {
            int e = tid + r * 256;
            int row = e >> 2, c4 = e & 3;
            ra[r] = *reinterpret_cast<const uint4*>(
                Abase + (size_t)(k0 + row) * astride + Acol + c4 * 8);
        }
        {
            int row = tid >> 2, c4 = tid & 3;
            rb = *reinterpret_cast<const uint4*>(
                g_Bx + (size_t)(v0 + row) * 1280 + Bcol + c4 * 8);
        }
    };
    auto store = [&](int buf) {
#pragma unroll
        for (int r = 0; r < 2; r++) {
            int e = tid + r * 256;
            int row = e >> 2, c4 = e & 3;
            *reinterpret_cast<uint4*>(&sA[buf][row * SAPAD + c4 * 8]) = ra[r];
        }
        {
            int row = tid >> 2, c4 = tid & 3;
            *reinterpret_cast<uint4*>(&sB[buf][row * SAPAD + c4 * 8]) = rb;
        }
    };

    load(0);
    store(0);

    for (int c = 0; c < 90; c++) {
        __syncthreads();
        if (c + 1 < 90) load(c + 1);
        const int buf = c & 1;
        const bool isQ = (c < 60);
#pragma unroll
        for (int ks = 0; ks < 2; ks++) {
            const int kc = ks * 16;
            u32 a[2][4], b[4][2];
#pragma unroll
            for (int mf = 0; mf < 2; mf++) {
                int rbse = warp_m * 32 + mf * 16;
                const __nv_bfloat16* p = &sA[buf][0];
                a[mf][0] = *reinterpret_cast<const u32*>(&p[(rbse + g)     * SAPAD + kc + 2 * t]);
                a[mf][1] = *reinterpret_cast<const u32*>(&p[(rbse + g + 8) * SAPAD + kc + 2 * t]);
                a[mf][2] = *reinterpret_cast<const u32*>(&p[(rbse + g)     * SAPAD + kc + 8 + 2 * t]);
                a[mf][3] = *reinterpret_cast<const u32*>(&p[(rbse + g + 8) * SAPAD + kc + 8 + 2 * t]);
            }
#pragma unroll
            for (int nf = 0; nf < 4; nf++) {
                int nrow = warp_n * 32 + nf * 8 + g;
                const __nv_bfloat16* p = &sB[buf][0];
                b[nf][0] = *reinterpret_cast<const u32*>(&p[nrow * SAPAD + kc + 2 * t]);
                b[nf][1] = *reinterpret_cast<const u32*>(&p[nrow * SAPAD + kc + 8 + 2 * t]);
            }
            if (isQ) {
#pragma unroll
                for (int mf = 0; mf < 2; mf++)
#pragma unroll
                    for (int nf = 0; nf < 4; nf++)
                        mma16816(accQ[mf][nf], a[mf], b[nf]);
            } else {
#pragma unroll
                for (int mf = 0; mf < 2; mf++)
#pragma unroll
                    for (int nf = 0; nf < 4; nf++)
                        mma16816(accT[mf][nf], a[mf], b[nf]);
            }
        }
        if (c + 1 < 90) store((c + 1) & 1);
    }

    // epilogue: d0={g,2t}, d1={g,2t+1}, d2={g+8,2t}, d3={g+8,2t+1}
#pragma unroll
    for (int mf = 0; mf < 2; mf++) {
        int k_lo = k0 + warp_m * 32 + mf * 16 + g;
        int k_hi = k_lo + 8;
        float c1l = 0.f, c2l = 0.f, cil = 0.f, ckl = 0.f;
        float c1h = 0.f, c2h = 0.f, cih = 0.f, ckh = 0.f;
        if (k_lo < K_N) { c1l = g_c1[k_lo]; c2l = g_c2[k_lo]; cil = g_capinv[k_lo]; ckl = g_constk[k_lo]; }
        if (k_hi < K_N) { c1h = g_c1[k_hi]; c2h = g_c2[k_hi]; cih = g_capinv[k_hi]; ckh = g_constk[k_hi]; }
#pragma unroll
        for (int nf = 0; nf < 4; nf++) {
            int v = v0 + warp_n * 32 + nf * 8 + 2 * t;
            if (v >= V_N) continue;
            // k_lo pair
            if (k_lo < K_N) {
                float q0 = accQ[mf][nf][0] + c1l;
                float t0 = accT[mf][nf][0] - c2l;
                float q1 = accQ[mf][nf][1] + c1l;
                float t1 = accT[mf][nf][1] - c2l;
                float2 r;
                r.x = ckl - 0.5f * (q0 - t0 * t0 * cil);
                r.y = ckl - 0.5f * (q1 - t1 * t1 * cil);
                *reinterpret_cast<float2*>(&g_logp[(size_t)k_lo * V_N + v]) = r;
            }
            if (k_hi < K_N) {
                float q0 = accQ[mf][nf][2] + c1h;
                float t0 = accT[mf][nf][2] - c2h;
                float q1 = accQ[mf][nf][3] + c1h;
                float t1 = accT[mf][nf][3] - c2h;
                float2 r;
                r.x = ckh - 0.5f * (q0 - t0 * t0 * cih);
                r.y = ckh - 0.5f * (q1 - t1 * t1 * cih);
                *reinterpret_cast<float2*>(&g_logp[(size_t)k_hi * V_N + v]) = r;
            }
        }
    }
}

// ---------------- kernel 4a: per-(topic, chunk) partial max/sum ----------------
#define NCH 8
#define CHV (V_N / NCH)   // 12500

__global__ void softmax_partial() {
    const int k = blockIdx.x;
    const int c = blockIdx.y;
    const int tid = threadIdx.x;
    const float4* p = reinterpret_cast<const float4*>(&g_logp[(size_t)k * V_N + c * CHV]);
    const int n4 = CHV / 4;

    float m = -3.4e38f;
    for (int f = tid; f < n4; f += 256) {
        float4 x = p[f];
        m = fmaxf(m, fmaxf(fmaxf(x.x, x.y), fmaxf(x.z, x.w)));
    }
    __shared__ float red[256];
    red[tid] = m;
    __syncthreads();
    for (int off = 128; off > 0; off >>= 1) {
        if (tid < off) red[tid] = fmaxf(red[tid], red[tid + off]);
        __syncthreads();
    }
    float M = red[0];
    __syncthreads();

    float s = 0.f;
    for (int f = tid; f < n4; f += 256) {
        float4 x = p[f];
        s += __expf(x.x - M) + __expf(x.y - M) + __expf(x.z - M) + __expf(x.w - M);
    }
    red[tid] = s;
    __syncthreads();
    for (int off = 128; off > 0; off >>= 1) {
        if (tid < off) red[tid] += red[tid + off];
        __syncthreads();
    }
    if (tid == 0) {
        g_pmax[k * NCH + c] = M;
        g_psum[k * NCH + c] = red[0];
    }
}

// ---------------- kernel 4b: merge partials -> g_softc ----------------
__global__ void softmax_merge() {
    int k = blockIdx.x * blockDim.x + threadIdx.x;
    if (k < K_N) {
        float M = -3.4e38f;
#pragma unroll
        for (int c = 0; c < NCH; c++) M = fmaxf(M, g_pmax[k * NCH + c]);
        float S = 0.f;
#pragma unroll
        for (int c = 0; c < NCH; c++)
            S += g_psum[k * NCH + c] * __expf(g_pmax[k * NCH + c] - M);
        g_softc[k] = M + logf(S);
    }
}

// ---------------- kernel 5: word_dist = sx @ softmax(logp), f32x2 over v ----------------
#define VT 64
#define BT 64
#define KC 8

__global__ __launch_bounds__(256) void out_gemm(float* __restrict__ out) {
    __shared__ float wt [KC][VT];
    __shared__ float sxs[KC][BT];

    const int b0 = blockIdx.x * BT;   // b fastest -> logp tile L2 reuse
    const int v0 = blockIdx.y * VT;
    const int tid = threadIdx.x;
    const int tv = tid & 15;
    const int tb = tid >> 4;

    u64 acc[4][2];
#pragma unroll
    for (int a = 0; a < 4; a++) { acc[a][0] = 0ull; acc[a][1] = 0ull; }

    for (int kc = 0; kc < K_N; kc += KC) {
        __syncthreads();
#pragma unroll
        for (int r = 0; r < 2; r++) {
            int e = tid + r * 256;
            int kk = e >> 6, vv = e & 63;
            int k = kc + kk;
            int v = v0 + vv;
            float x = (v < V_N) ? g_logp[(size_t)k * V_N + v] : -3.0e38f;
            wt[kk][vv] = __expf(x - g_softc[k]);
        }
#pragma unroll
        for (int r = 0; r < 2; r++) {
            int e = tid + r * 256;
            int kk = e >> 6, bb = e & 63;
            sxs[kk][bb] = g_sxT[(kc + kk) * B_N + b0 + bb];
        }
        __syncthreads();
#pragma unroll
        for (int kk = 0; kk < KC; kk++) {
            const u64* ap = reinterpret_cast<const u64*>(&wt[kk][tv * 4]);
            u64 a0 = ap[0], a1 = ap[1];
            float4 s4 = *reinterpret_cast<const float4*>(&sxs[kk][tb * 4]);
            u64 sd0 = pack2(s4.x, s4.x);
            u64 sd1 = pack2(s4.y, s4.y);
            u64 sd2 = pack2(s4.z, s4.z);
            u64 sd3 = pack2(s4.w, s4.w);
            acc[0][0] = fma2(sd0, a0, acc[0][0]); acc[0][1] = fma2(sd0, a1, acc[0][1]);
            acc[1][0] = fma2(sd1, a0, acc[1][0]); acc[1][1] = fma2(sd1, a1, acc[1][1]);
            acc[2][0] = fma2(sd2, a0, acc[2][0]); acc[2][1] = fma2(sd2, a1, acc[2][1]);
            acc[3][0] = fma2(sd3, a0, acc[3][0]); acc[3][1] = fma2(sd3, a1, acc[3][1]);
        }
    }

    const int vw = v0 + tv * 4;
    if (vw < V_N) {
#pragma unroll
        for (int jb = 0; jb < 4; jb++) {
            int b = b0 + tb * 4 + jb;
            float r0, r1, r2, r3;
            unpack2(acc[jb][0], r0, r1);
            unpack2(acc[jb][1], r2, r3);
            *reinterpret_cast<float4*>(&out[(size_t)b * OUTSTRIDE + K_N + vw]) =
                make_float4(r0, r1, r2, r3);
        }
    }
}

// ---------------- launch ----------------
extern "C" void kernel_launch(void* const* d_in, const int* in_sizes, int n_in,
                              void* d_out, int out_size) {
    const float* sx = (const float*)d_in[0];   // (256, 200)
    const float* wv = (const float*)d_in[1];   // (100000, 300)
    const float* mu = (const float*)d_in[2];   // (200, 300)
    const float* cf = (const float*)d_in[3];   // (200, 300)
    const float* cd = (const float*)d_in[4];   // (200, 300)
    float* out = (float*)d_out;                // (256, 100200)

    topic_prep<<<K_N, 128>>>(mu, cf, cd);
    wsplit<<<(V_N * 40 + 255) / 256, 256>>>(wv);
    sx_prep<<<(B_N * K_N + 255) / 256, 256>>>(sx, out);
    logp_mma<<<dim3(2, VTILES), 256>>>();
    softmax_partial<<<dim3(K_N, NCH), 256>>>();
    softmax_merge<<<1, 256>>>();
    out_gemm<<<dim3(B_N / BT, (V_N + VT - 1) / VT), 256>>>(out);
}

// round 15
// speedup vs baseline: 1.6700x; 1.1127x over previous
#include <cuda_runtime.h>
#include <cuda_bf16.h>
#include <math.h>
#include <stdint.h>

#define V_N 100000
#define D_N 300
#define K_N 200
#define B_N 256
#define OUTSTRIDE (K_N + V_N)

#define VTILES 1563
#define VPAD (VTILES * 64)        // 100032

typedef unsigned long long u64;
typedef unsigned int u32;

// ---------------- f32x2 packed helpers (for out_gemm) ----------------
__device__ __forceinline__ u64 pack2(float lo, float hi) {
    u64 r;
    asm("mov.b64 %0, {%1, %2};" : "=l"(r)
        : "r"(__float_as_uint(lo)), "r"(__float_as_uint(hi)));
    return r;
}
__device__ __forceinline__ void unpack2(u64 v, float& lo, float& hi) {
    u32 a, b;
    asm("mov.b64 {%0, %1}, %2;" : "=r"(a), "=r"(b) : "l"(v));
    lo = __uint_as_float(a);
    hi = __uint_as_float(b);
}
__device__ __forceinline__ u64 fma2(u64 a, u64 b, u64 c) {
    u64 d;
    asm("fma.rn.f32x2 %0, %1, %2, %3;" : "=l"(d) : "l"(a), "l"(b), "l"(c));
    return d;
}

// ---------------- warp mma.sync bf16 + ldmatrix + cp.async ----------------
__device__ __forceinline__ void mma16816(float* d, const u32* a, const u32* b) {
    asm volatile(
        "mma.sync.aligned.m16n8k16.row.col.f32.bf16.bf16.f32 "
        "{%0,%1,%2,%3}, {%4,%5,%6,%7}, {%8,%9}, {%0,%1,%2,%3};"
        : "+f"(d[0]), "+f"(d[1]), "+f"(d[2]), "+f"(d[3])
        : "r"(a[0]), "r"(a[1]), "r"(a[2]), "r"(a[3]), "r"(b[0]), "r"(b[1]));
}
__device__ __forceinline__ void ldsm4(u32* r, u32 addr) {
    asm volatile("ldmatrix.sync.aligned.m8n8.x4.shared.b16 {%0,%1,%2,%3}, [%4];"
        : "=r"(r[0]), "=r"(r[1]), "=r"(r[2]), "=r"(r[3]) : "r"(addr));
}
__device__ __forceinline__ void cpasync16(u32 dst, const void* src) {
    asm volatile("cp.async.cg.shared.global [%0], [%1], 16;" :: "r"(dst), "l"(src));
}
#define CP_COMMIT() asm volatile("cp.async.commit_group;" ::: "memory")
#define CP_WAIT0()  asm volatile("cp.async.wait_group 0;" ::: "memory")

__device__ __forceinline__ u32 smem_u32(const void* p) {
    u32 a;
    asm("{ .reg .u64 t; cvta.to.shared.u64 t, %1; cvt.u32.u64 %0, t; }"
        : "=r"(a) : "l"(p));
    return a;
}

// ---------------- scratch (static device globals; BSS zero-init) ----------------
__device__ float g_logp[(size_t)K_N * V_N];                 // 80 MB [K][V]
// A operands, 256 k-rows. Aqm cols [0,1280): [dinv_h(320)|m2_h(320)|dinv_l(320)|m2_l(320)]
__device__ __align__(256) __nv_bfloat16 g_Aqm[256 * 1280];
// At cols [0,640): [u_h(320)|u_l(320)]
__device__ __align__(256) __nv_bfloat16 g_At[256 * 640];
// B operand [VPAD][1280]: [w2_h(320)|w_h(320)|w2_l(320)|w_l(320)]
__device__ __align__(256) __nv_bfloat16 g_Bx[(size_t)VPAD * 1280];
__device__ float g_c1[K_N], g_c2[K_N], g_capinv[K_N], g_constk[K_N];
__device__ float g_softc[K_N];
__device__ float g_pmax[K_N * 8];
__device__ float g_psum[K_N * 8];
__device__ float g_sxT[K_N * B_N];

__device__ __forceinline__ void bsplit(float x, __nv_bfloat16& hi, __nv_bfloat16& lo) {
    hi = __float2bfloat16(x);
    lo = __float2bfloat16(x - __bfloat162float(hi));
}

// ---------------- kernel 1: per-topic precompute + A operand split ----------------
__global__ void topic_prep(const float* __restrict__ mu,
                           const float* __restrict__ cf,
                           const float* __restrict__ cd) {
    int k = blockIdx.x;
    int tid = threadIdx.x;
    float capa = 0.f, ld = 0.f, c1 = 0.f, c2 = 0.f;
    for (int d = tid; d < D_N; d += blockDim.x) {
        float diag = cd[k * D_N + d];
        float dinv = 1.0f / diag;
        float m    = mu[k * D_N + d];
        float w    = cf[k * D_N + d];
        float u    = w * dinv;
        float mdi  = m * dinv;
        float m2   = -2.0f * mdi;
        __nv_bfloat16 hi, lo;
        bsplit(dinv, hi, lo);
        g_Aqm[k * 1280 + d]        = hi;
        g_Aqm[k * 1280 + 640 + d]  = lo;
        bsplit(m2, hi, lo);
        g_Aqm[k * 1280 + 320 + d]  = hi;
        g_Aqm[k * 1280 + 960 + d]  = lo;
        bsplit(u, hi, lo);
        g_At[k * 640 + d]          = hi;
        g_At[k * 640 + 320 + d]    = lo;
        capa += w * u;
        ld   += logf(diag);
        c1   += m * mdi;
        c2   += m * u;
    }
    __shared__ float s[4][128];
    s[0][tid] = capa; s[1][tid] = ld; s[2][tid] = c1; s[3][tid] = c2;
    __syncthreads();
    for (int off = 64; off > 0; off >>= 1) {
        if (tid < off) {
            s[0][tid] += s[0][tid + off];
            s[1][tid] += s[1][tid + off];
            s[2][tid] += s[2][tid + off];
            s[3][tid] += s[3][tid + off];
        }
        __syncthreads();
    }
    if (tid == 0) {
        float cap    = 1.0f + s[0][0];
        float logdet = s[1][0] + logf(cap);
        g_c1[k]     = s[2][0];
        g_c2[k]     = s[3][0];
        g_capinv[k] = 1.0f / cap;
        const float LOG2PI = 1.8378770664093453f;
        g_constk[k] = -0.5f * ((float)D_N * LOG2PI + logdet);
    }
}

// ---------------- kernel 1b: word-vector bf16 hi/lo split (+ squares) ----------------
__global__ void wsplit(const float* __restrict__ wv) {
    int idx = blockIdx.x * blockDim.x + threadIdx.x;
    if (idx >= V_N * 40) return;
    int v    = idx / 40;
    int dblk = idx - v * 40;
    int d0   = dblk * 8;

    __align__(16) __nv_bfloat16 wh[8], wl[8], w2h[8], w2l[8];
#pragma unroll
    for (int e = 0; e < 8; e++) {
        int d = d0 + e;
        float w = (d < D_N) ? wv[(size_t)v * D_N + d] : 0.f;
        float w2 = w * w;
        bsplit(w, wh[e], wl[e]);
        bsplit(w2, w2h[e], w2l[e]);
    }
    size_t base = (size_t)v * 1280 + d0;
    *reinterpret_cast<uint4*>(&g_Bx[base])        = *reinterpret_cast<uint4*>(w2h);
    *reinterpret_cast<uint4*>(&g_Bx[base + 320])  = *reinterpret_cast<uint4*>(wh);
    *reinterpret_cast<uint4*>(&g_Bx[base + 640])  = *reinterpret_cast<uint4*>(w2l);
    *reinterpret_cast<uint4*>(&g_Bx[base + 960])  = *reinterpret_cast<uint4*>(wl);
}

// ---------------- kernel 2: copy sampled_x into out[:, :K] + transpose ----------------
__global__ void sx_prep(const float* __restrict__ sx, float* __restrict__ out) {
    int idx = blockIdx.x * blockDim.x + threadIdx.x;
    if (idx < B_N * K_N) {
        int b = idx / K_N, k = idx % K_N;
        float v = sx[idx];
        out[(size_t)b * OUTSTRIDE + k] = v;
        g_sxT[k * B_N + b] = v;
    }
}

// ---------------- kernel 3: logp via mma.sync + ldmatrix + cp.async ----------------
#define SAPITCH 40                 // bf16 elements per smem row (80 B, conflict-free)
#define ABUF (128 * SAPITCH)
#define BBUF (64 * SAPITCH)

__global__ __launch_bounds__(256, 2) void logp_mma() {
    __shared__ __nv_bfloat16 sA[2][ABUF];
    __shared__ __nv_bfloat16 sB[2][BBUF];

    const int tid = threadIdx.x;
    const int wid = tid >> 5;
    const int lid = tid & 31;
    const int g   = lid >> 2;
    const int t   = lid & 3;
    const int warp_m = wid & 3;    // k rows warp_m*32
    const int warp_n = wid >> 2;   // v cols warp_n*32

    const int k0 = blockIdx.x * 128;
    const int v0 = blockIdx.y * 64;

    const u32 sAb = smem_u32(&sA[0][0]);
    const u32 sBb = smem_u32(&sB[0][0]);

    // cp.async destination/source (thread-fixed)
    const int rowA = tid >> 2;          // 0..63 (second copy +64)
    const int c4   = tid & 3;           // 16B column within 32-elem chunk
    const u32 dstA0 = sAb + (u32)((rowA * SAPITCH + c4 * 8) * 2);
    const u32 dstA1 = sAb + (u32)(((rowA + 64) * SAPITCH + c4 * 8) * 2);
    const u32 dstB  = sBb + (u32)((rowA * SAPITCH + c4 * 8) * 2);   // rowA==tid>>2 == rowB
    const size_t offQm0 = (size_t)(k0 + rowA) * 1280 + c4 * 8;
    const size_t offQm1 = (size_t)(k0 + rowA + 64) * 1280 + c4 * 8;
    const size_t offT0  = (size_t)(k0 + rowA) * 640 + c4 * 8;
    const size_t offT1  = (size_t)(k0 + rowA + 64) * 640 + c4 * 8;
    const size_t offB   = (size_t)(v0 + rowA) * 1280 + c4 * 8;

    // ldmatrix lane addresses (thread-fixed)
    u32 aAddr[2], bAddr[2];
    {
        int r8 = (lid & 7) + ((lid >> 3) & 1) * 8;
        int ko = (lid >> 4) * 8;
        aAddr[0] = sAb + (u32)(((warp_m * 32 +  0 + r8) * SAPITCH + ko) * 2);
        aAddr[1] = sAb + (u32)(((warp_m * 32 + 16 + r8) * SAPITCH + ko) * 2);
        int rb8 = lid & 7;
        int kob = ((lid >> 3) & 1) * 8;
        int nfs = (lid >> 4) & 1;
        bAddr[0] = sBb + (u32)(((warp_n * 32 + (0 + nfs) * 8 + rb8) * SAPITCH + kob) * 2);
        bAddr[1] = sBb + (u32)(((warp_n * 32 + (2 + nfs) * 8 + rb8) * SAPITCH + kob) * 2);
    }

    float accQ[2][4][4], accT[2][4][4];
#pragma unroll
    for (int mf = 0; mf < 2; mf++)
#pragma unroll
        for (int nf = 0; nf < 4; nf++)
#pragma unroll
            for (int e = 0; e < 4; e++) { accQ[mf][nf][e] = 0.f; accT[mf][nf][e] = 0.f; }

    // chunk schedule: c<60 -> qm (3 passes x 20); else t (3 passes x 10)
    auto issue = [&](int c) {
        int buf = c & 1;
        u32 boA = (u32)(buf * ABUF * 2);
        u32 boB = (u32)(buf * BBUF * 2);
        int Acol, Bcol;
        bool isQm;
        if (c < 60) {
            int p = c / 20, cc = c - p * 20;
            isQm = true;
            Acol = ((p == 2) ? 640 : 0) + cc * 32;
            Bcol = ((p == 1) ? 640 : 0) + cc * 32;
        } else {
            int c2 = c - 60;
            int p = c2 / 10, cc = c2 - p * 10;
            isQm = false;
            Acol = ((p == 2) ? 320 : 0) + cc * 32;
            Bcol = ((p == 1) ? 960 : 320) + cc * 32;
        }
        if (isQm) {
            cpasync16(dstA0 + boA, g_Aqm + offQm0 + Acol);
            cpasync16(dstA1 + boA, g_Aqm + offQm1 + Acol);
        } else {
            cpasync16(dstA0 + boA, g_At + offT0 + Acol);
            cpasync16(dstA1 + boA, g_At + offT1 + Acol);
        }
        cpasync16(dstB + boB, g_Bx + offB + Bcol);
        CP_COMMIT();
    };

    issue(0);

    for (int c = 0; c < 90; c++) {
        CP_WAIT0();
        __syncthreads();
        if (c + 1 < 90) issue(c + 1);

        const int buf = c & 1;
        const u32 aoff = (u32)(buf * ABUF * 2);
        const u32 boff = (u32)(buf * BBUF * 2);
        const bool isQ = (c < 60);
#pragma unroll
        for (int ks = 0; ks < 2; ks++) {
            const u32 kb = (u32)(ks * 32);   // 16 bf16 = 32 bytes
            u32 af0[4], af1[4], bf0[4], bf1[4];
            ldsm4(af0, aAddr[0] + aoff + kb);
            ldsm4(af1, aAddr[1] + aoff + kb);
            ldsm4(bf0, bAddr[0] + boff + kb);
            ldsm4(bf1, bAddr[1] + boff + kb);
            if (isQ) {
                mma16816(accQ[0][0], af0, &bf0[0]);
                mma16816(accQ[0][1], af0, &bf0[2]);
                mma16816(accQ[0][2], af0, &bf1[0]);
                mma16816(accQ[0][3], af0, &bf1[2]);
                mma16816(accQ[1][0], af1, &bf0[0]);
                mma16816(accQ[1][1], af1, &bf0[2]);
                mma16816(accQ[1][2], af1, &bf1[0]);
                mma16816(accQ[1][3], af1, &bf1[2]);
            } else {
                mma16816(accT[0][0], af0, &bf0[0]);
                mma16816(accT[0][1], af0, &bf0[2]);
                mma16816(accT[0][2], af0, &bf1[0]);
                mma16816(accT[0][3], af0, &bf1[2]);
                mma16816(accT[1][0], af1, &bf0[0]);
                mma16816(accT[1][1], af1, &bf0[2]);
                mma16816(accT[1][2], af1, &bf1[0]);
                mma16816(accT[1][3], af1, &bf1[2]);
            }
        }
    }

    // epilogue: fragment (mf,nf) element e: rows k = base+g (e0,e1) / base+g+8 (e2,e3),
    // cols v = nf*8 + 2t (+0/+1)
#pragma unroll
    for (int mf = 0; mf < 2; mf++) {
        int k_lo = k0 + warp_m * 32 + mf * 16 + g;
        int k_hi = k_lo + 8;
        float c1l = 0.f, c2l = 0.f, cil = 0.f, ckl = 0.f;
        float c1h = 0.f, c2h = 0.f, cih = 0.f, ckh = 0.f;
        if (k_lo < K_N) { c1l = g_c1[k_lo]; c2l = g_c2[k_lo]; cil = g_capinv[k_lo]; ckl = g_constk[k_lo]; }
        if (k_hi < K_N) { c1h = g_c1[k_hi]; c2h = g_c2[k_hi]; cih = g_capinv[k_hi]; ckh = g_constk[k_hi]; }
#pragma unroll
        for (int nf = 0; nf < 4; nf++) {
            int v = v0 + warp_n * 32 + nf * 8 + 2 * t;
            if (v >= V_N) continue;
            if (k_lo < K_N) {
                float q0 = accQ[mf][nf][0] + c1l;
                float t0 = accT[mf][nf][0] - c2l;
                float q1 = accQ[mf][nf][1] + c1l;
                float t1 = accT[mf][nf][1] - c2l;
                float2 r;
                r.x = ckl - 0.5f * (q0 - t0 * t0 * cil);
                r.y = ckl - 0.5f * (q1 - t1 * t1 * cil);
                *reinterpret_cast<float2*>(&g_logp[(size_t)k_lo * V_N + v]) = r;
            }
            if (k_hi < K_N) {
                float q0 = accQ[mf][nf][2] + c1h;
                float t0 = accT[mf][nf][2] - c2h;
                float q1 = accQ[mf][nf][3] + c1h;
                float t1 = accT[mf][nf][3] - c2h;
                float2 r;
                r.x = ckh - 0.5f * (q0 - t0 * t0 * cih);
                r.y = ckh - 0.5f * (q1 - t1 * t1 * cih);
                *reinterpret_cast<float2*>(&g_logp[(size_t)k_hi * V_N + v]) = r;
            }
        }
    }
}

// ---------------- kernel 4a: per-(topic, chunk) partial max/sum ----------------
#define NCH 8
#define CHV (V_N / NCH)   // 12500

__global__ void softmax_partial() {
    const int k = blockIdx.x;
    const int c = blockIdx.y;
    const int tid = threadIdx.x;
    const float4* p = reinterpret_cast<const float4*>(&g_logp[(size_t)k * V_N + c * CHV]);
    const int n4 = CHV / 4;

    float m = -3.4e38f;
    for (int f = tid; f < n4; f += 256) {
        float4 x = p[f];
        m = fmaxf(m, fmaxf(fmaxf(x.x, x.y), fmaxf(x.z, x.w)));
    }
    __shared__ float red[256];
    red[tid] = m;
    __syncthreads();
    for (int off = 128; off > 0; off >>= 1) {
        if (tid < off) red[tid] = fmaxf(red[tid], red[tid + off]);
        __syncthreads();
    }
    float M = red[0];
    __syncthreads();

    float s = 0.f;
    for (int f = tid; f < n4; f += 256) {
        float4 x = p[f];
        s += __expf(x.x - M) + __expf(x.y - M) + __expf(x.z - M) + __expf(x.w - M);
    }
    red[tid] = s;
    __syncthreads();
    for (int off = 128; off > 0; off >>= 1) {
        if (tid < off) red[tid] += red[tid + off];
        __syncthreads();
    }
    if (tid == 0) {
        g_pmax[k * NCH + c] = M;
        g_psum[k * NCH + c] = red[0];
    }
}

// ---------------- kernel 4b: merge partials -> g_softc ----------------
__global__ void softmax_merge() {
    int k = blockIdx.x * blockDim.x + threadIdx.x;
    if (k < K_N) {
        float M = -3.4e38f;
#pragma unroll
        for (int c = 0; c < NCH; c++) M = fmaxf(M, g_pmax[k * NCH + c]);
        float S = 0.f;
#pragma unroll
        for (int c = 0; c < NCH; c++)
            S += g_psum[k * NCH + c] * __expf(g_pmax[k * NCH + c] - M);
        g_softc[k] = M + logf(S);
    }
}

// ---------------- kernel 5: word_dist = sx @ softmax(logp), f32x2 over v ----------------
#define VT 64
#define BT 64
#define KC 8

__global__ __launch_bounds__(256) void out_gemm(float* __restrict__ out) {
    __shared__ float wt [KC][VT];
    __shared__ float sxs[KC][BT];

    const int b0 = blockIdx.x * BT;   // b fastest -> logp tile L2 reuse
    const int v0 = blockIdx.y * VT;
    const int tid = threadIdx.x;
    const int tv = tid & 15;
    const int tb = tid >> 4;

    u64 acc[4][2];
#pragma unroll
    for (int a = 0; a < 4; a++) { acc[a][0] = 0ull; acc[a][1] = 0ull; }

    for (int kc = 0; kc < K_N; kc += KC) {
        __syncthreads();
#pragma unroll
        for (int r = 0; r < 2; r++) {
            int e = tid + r * 256;
            int kk = e >> 6, vv = e & 63;
            int k = kc + kk;
            int v = v0 + vv;
            float x = (v < V_N) ? g_logp[(size_t)k * V_N + v] : -3.0e38f;
            wt[kk][vv] = __expf(x - g_softc[k]);
        }
#pragma unroll
        for (int r = 0; r < 2; r++) {
            int e = tid + r * 256;
            int kk = e >> 6, bb = e & 63;
            sxs[kk][bb] = g_sxT[(kc + kk) * B_N + b0 + bb];
        }
        __syncthreads();
#pragma unroll
        for (int kk = 0; kk < KC; kk++) {
            const u64* ap = reinterpret_cast<const u64*>(&wt[kk][tv * 4]);
            u64 a0 = ap[0], a1 = ap[1];
            float4 s4 = *reinterpret_cast<const float4*>(&sxs[kk][tb * 4]);
            u64 sd0 = pack2(s4.x, s4.x);
            u64 sd1 = pack2(s4.y, s4.y);
            u64 sd2 = pack2(s4.z, s4.z);
            u64 sd3 = pack2(s4.w, s4.w);
            acc[0][0] = fma2(sd0, a0, acc[0][0]); acc[0][1] = fma2(sd0, a1, acc[0][1]);
            acc[1][0] = fma2(sd1, a0, acc[1][0]); acc[1][1] = fma2(sd1, a1, acc[1][1]);
            acc[2][0] = fma2(sd2, a0, acc[2][0]); acc[2][1] = fma2(sd2, a1, acc[2][1]);
            acc[3][0] = fma2(sd3, a0, acc[3][0]); acc[3][1] = fma2(sd3, a1, acc[3][1]);
        }
    }

    const int vw = v0 + tv * 4;
    if (vw < V_N) {
#pragma unroll
        for (int jb = 0; jb < 4; jb++) {
            int b = b0 + tb * 4 + jb;
            float r0, r1, r2, r3;
            unpack2(acc[jb][0], r0, r1);
            unpack2(acc[jb][1], r2, r3);
            *reinterpret_cast<float4*>(&out[(size_t)b * OUTSTRIDE + K_N + vw]) =
                make_float4(r0, r1, r2, r3);
        }
    }
}

// ---------------- launch ----------------
extern "C" void kernel_launch(void* const* d_in, const int* in_sizes, int n_in,
                              void* d_out, int out_size) {
    const float* sx = (const float*)d_in[0];   // (256, 200)
    const float* wv = (const float*)d_in[1];   // (100000, 300)
    const float* mu = (const float*)d_in[2];   // (200, 300)
    const float* cf = (const float*)d_in[3];   // (200, 300)
    const float* cd = (const float*)d_in[4];   // (200, 300)
    float* out = (float*)d_out;                // (256, 100200)

    topic_prep<<<K_N, 128>>>(mu, cf, cd);
    wsplit<<<(V_N * 40 + 255) / 256, 256>>>(wv);
    sx_prep<<<(B_N * K_N + 255) / 256, 256>>>(sx, out);
    logp_mma<<<dim3(2, VTILES), 256>>>();
    softmax_partial<<<dim3(K_N, NCH), 256>>>();
    softmax_merge<<<1, 256>>>();
    out_gemm<<<dim3(B_N / BT, (V_N + VT - 1) / VT), 256>>>(out);
}

// round 16
// speedup vs baseline: 1.6712x; 1.0007x over previous
#include <cuda_runtime.h>
#include <cuda_bf16.h>
#include <math.h>
#include <stdint.h>

#define V_N 100000
#define D_N 300
#define K_N 200
#define B_N 256
#define OUTSTRIDE (K_N + V_N)

#define VTILES 1563
#define VPAD (VTILES * 64)        // 100032

typedef unsigned long long u64;
typedef unsigned int u32;

// ---------------- f32x2 packed helpers (for out_gemm) ----------------
__device__ __forceinline__ u64 pack2(float lo, float hi) {
    u64 r;
    asm("mov.b64 %0, {%1, %2};" : "=l"(r)
        : "r"(__float_as_uint(lo)), "r"(__float_as_uint(hi)));
    return r;
}
__device__ __forceinline__ void unpack2(u64 v, float& lo, float& hi) {
    u32 a, b;
    asm("mov.b64 {%0, %1}, %2;" : "=r"(a), "=r"(b) : "l"(v));
    lo = __uint_as_float(a);
    hi = __uint_as_float(b);
}
__device__ __forceinline__ u64 fma2(u64 a, u64 b, u64 c) {
    u64 d;
    asm("fma.rn.f32x2 %0, %1, %2, %3;" : "=l"(d) : "l"(a), "l"(b), "l"(c));
    return d;
}

// ---------------- warp mma.sync bf16 + ldmatrix + cp.async ----------------
__device__ __forceinline__ void mma16816(float* d, const u32* a, const u32* b) {
    asm volatile(
        "mma.sync.aligned.m16n8k16.row.col.f32.bf16.bf16.f32 "
        "{%0,%1,%2,%3}, {%4,%5,%6,%7}, {%8,%9}, {%0,%1,%2,%3};"
        : "+f"(d[0]), "+f"(d[1]), "+f"(d[2]), "+f"(d[3])
        : "r"(a[0]), "r"(a[1]), "r"(a[2]), "r"(a[3]), "r"(b[0]), "r"(b[1]));
}
__device__ __forceinline__ void ldsm4(u32* r, u32 addr) {
    asm volatile("ldmatrix.sync.aligned.m8n8.x4.shared.b16 {%0,%1,%2,%3}, [%4];"
        : "=r"(r[0]), "=r"(r[1]), "=r"(r[2]), "=r"(r[3]) : "r"(addr));
}
__device__ __forceinline__ void cpasync16(u32 dst, const void* src) {
    asm volatile("cp.async.cg.shared.global [%0], [%1], 16;" :: "r"(dst), "l"(src));
}
#define CP_COMMIT() asm volatile("cp.async.commit_group;" ::: "memory")
#define CP_WAIT0()  asm volatile("cp.async.wait_group 0;" ::: "memory")

__device__ __forceinline__ u32 smem_u32(const void* p) {
    u32 a;
    asm("{ .reg .u64 t; cvta.to.shared.u64 t, %1; cvt.u32.u64 %0, t; }"
        : "=r"(a) : "l"(p));
    return a;
}

// ---------------- scratch (static device globals; BSS zero-init) ----------------
__device__ float g_logp[(size_t)K_N * V_N];                 // 80 MB [K][V]
// A operands, 256 k-rows. Aqm cols [0,1280): [dinv_h(320)|m2_h(320)|dinv_l(320)|m2_l(320)]
__device__ __align__(256) __nv_bfloat16 g_Aqm[256 * 1280];
// At cols [0,640): [u_h(320)|u_l(320)]
__device__ __align__(256) __nv_bfloat16 g_At[256 * 640];
// B operand [VPAD][1280]: [w2_h(320)|w_h(320)|w2_l(320)|w_l(320)]
__device__ __align__(256) __nv_bfloat16 g_Bx[(size_t)VPAD * 1280];
__device__ float g_c1[K_N], g_c2[K_N], g_capinv[K_N], g_constk[K_N];
__device__ float g_softc[K_N];
__device__ float g_pmax[K_N * 8];
__device__ float g_psum[K_N * 8];
__device__ float g_sxT[K_N * B_N];

__device__ __forceinline__ void bsplit(float x, __nv_bfloat16& hi, __nv_bfloat16& lo) {
    hi = __float2bfloat16(x);
    lo = __float2bfloat16(x - __bfloat162float(hi));
}

// ---------------- kernel 1: per-topic precompute + A operand split ----------------
__global__ void topic_prep(const float* __restrict__ mu,
                           const float* __restrict__ cf,
                           const float* __restrict__ cd) {
    int k = blockIdx.x;
    int tid = threadIdx.x;
    float capa = 0.f, ld = 0.f, c1 = 0.f, c2 = 0.f;
    for (int d = tid; d < D_N; d += blockDim.x) {
        float diag = cd[k * D_N + d];
        float dinv = 1.0f / diag;
        float m    = mu[k * D_N + d];
        float w    = cf[k * D_N + d];
        float u    = w * dinv;
        float mdi  = m * dinv;
        float m2   = -2.0f * mdi;
        __nv_bfloat16 hi, lo;
        bsplit(dinv, hi, lo);
        g_Aqm[k * 1280 + d]        = hi;
        g_Aqm[k * 1280 + 640 + d]  = lo;
        bsplit(m2, hi, lo);
        g_Aqm[k * 1280 + 320 + d]  = hi;
        g_Aqm[k * 1280 + 960 + d]  = lo;
        bsplit(u, hi, lo);
        g_At[k * 640 + d]          = hi;
        g_At[k * 640 + 320 + d]    = lo;
        capa += w * u;
        ld   += logf(diag);
        c1   += m * mdi;
        c2   += m * u;
    }
    __shared__ float s[4][128];
    s[0][tid] = capa; s[1][tid] = ld; s[2][tid] = c1; s[3][tid] = c2;
    __syncthreads();
    for (int off = 64; off > 0; off >>= 1) {
        if (tid < off) {
            s[0][tid] += s[0][tid + off];
            s[1][tid] += s[1][tid + off];
            s[2][tid] += s[2][tid + off];
            s[3][tid] += s[3][tid + off];
        }
        __syncthreads();
    }
    if (tid == 0) {
        float cap    = 1.0f + s[0][0];
        float logdet = s[1][0] + logf(cap);
        g_c1[k]     = s[2][0];
        g_c2[k]     = s[3][0];
        g_capinv[k] = 1.0f / cap;
        const float LOG2PI = 1.8378770664093453f;
        g_constk[k] = -0.5f * ((float)D_N * LOG2PI + logdet);
    }
}

// ---------------- kernel 1b: word-vector bf16 hi/lo split (+ squares) ----------------
__global__ void wsplit(const float* __restrict__ wv) {
    int idx = blockIdx.x * blockDim.x + threadIdx.x;
    if (idx >= V_N * 40) return;
    int v    = idx / 40;
    int dblk = idx - v * 40;
    int d0   = dblk * 8;

    __align__(16) __nv_bfloat16 wh[8], wl[8], w2h[8], w2l[8];
#pragma unroll
    for (int e = 0; e < 8; e++) {
        int d = d0 + e;
        float w = (d < D_N) ? wv[(size_t)v * D_N + d] : 0.f;
        float w2 = w * w;
        bsplit(w, wh[e], wl[e]);
        bsplit(w2, w2h[e], w2l[e]);
    }
    size_t base = (size_t)v * 1280 + d0;
    *reinterpret_cast<uint4*>(&g_Bx[base])        = *reinterpret_cast<uint4*>(w2h);
    *reinterpret_cast<uint4*>(&g_Bx[base + 320])  = *reinterpret_cast<uint4*>(wh);
    *reinterpret_cast<uint4*>(&g_Bx[base + 640])  = *reinterpret_cast<uint4*>(w2l);
    *reinterpret_cast<uint4*>(&g_Bx[base + 960])  = *reinterpret_cast<uint4*>(wl);
}

// ---------------- kernel 2: copy sampled_x into out[:, :K] + transpose ----------------
__global__ void sx_prep(const float* __restrict__ sx, float* __restrict__ out) {
    int idx = blockIdx.x * blockDim.x + threadIdx.x;
    if (idx < B_N * K_N) {
        int b = idx / K_N, k = idx % K_N;
        float v = sx[idx];
        out[(size_t)b * OUTSTRIDE + k] = v;
        g_sxT[k * B_N + b] = v;
    }
}

// ---------------- kernel 3: logp via mma.sync + ldmatrix + cp.async ----------------
#define SAPITCH 40                 // bf16 elements per smem row (80 B, conflict-free)
#define ABUF (128 * SAPITCH)
#define BBUF (64 * SAPITCH)

__global__ __launch_bounds__(256, 2) void logp_mma() {
    __shared__ __nv_bfloat16 sA[2][ABUF];
    __shared__ __nv_bfloat16 sB[2][BBUF];

    const int tid = threadIdx.x;
    const int wid = tid >> 5;
    const int lid = tid & 31;
    const int g   = lid >> 2;
    const int t   = lid & 3;
    const int warp_m = wid & 3;    // k rows warp_m*32
    const int warp_n = wid >> 2;   // v cols warp_n*32

    const int k0 = blockIdx.x * 128;
    const int v0 = blockIdx.y * 64;

    const u32 sAb = smem_u32(&sA[0][0]);
    const u32 sBb = smem_u32(&sB[0][0]);

    // cp.async destination/source (thread-fixed)
    const int rowA = tid >> 2;          // 0..63 (second copy +64)
    const int c4   = tid & 3;           // 16B column within 32-elem chunk
    const u32 dstA0 = sAb + (u32)((rowA * SAPITCH + c4 * 8) * 2);
    const u32 dstA1 = sAb + (u32)(((rowA + 64) * SAPITCH + c4 * 8) * 2);
    const u32 dstB  = sBb + (u32)((rowA * SAPITCH + c4 * 8) * 2);   // rowA==tid>>2 == rowB
    const size_t offQm0 = (size_t)(k0 + rowA) * 1280 + c4 * 8;
    const size_t offQm1 = (size_t)(k0 + rowA + 64) * 1280 + c4 * 8;
    const size_t offT0  = (size_t)(k0 + rowA) * 640 + c4 * 8;
    const size_t offT1  = (size_t)(k0 + rowA + 64) * 640 + c4 * 8;
    const size_t offB   = (size_t)(v0 + rowA) * 1280 + c4 * 8;

    // ldmatrix lane addresses (thread-fixed)
    u32 aAddr[2], bAddr[2];
    {
        int r8 = (lid & 7) + ((lid >> 3) & 1) * 8;
        int ko = (lid >> 4) * 8;
        aAddr[0] = sAb + (u32)(((warp_m * 32 +  0 + r8) * SAPITCH + ko) * 2);
        aAddr[1] = sAb + (u32)(((warp_m * 32 + 16 + r8) * SAPITCH + ko) * 2);
        int rb8 = lid & 7;
        int kob = ((lid >> 3) & 1) * 8;
        int nfs = (lid >> 4) & 1;
        bAddr[0] = sBb + (u32)(((warp_n * 32 + (0 + nfs) * 8 + rb8) * SAPITCH + kob) * 2);
        bAddr[1] = sBb + (u32)(((warp_n * 32 + (2 + nfs) * 8 + rb8) * SAPITCH + kob) * 2);
    }

    float accQ[2][4][4], accT[2][4][4];
#pragma unroll
    for (int mf = 0; mf < 2; mf++)
#pragma unroll
        for (int nf = 0; nf < 4; nf++)
#pragma unroll
            for (int e = 0; e < 4; e++) { accQ[mf][nf][e] = 0.f; accT[mf][nf][e] = 0.f; }

    // chunk schedule: c<60 -> qm (3 passes x 20); else t (3 passes x 10)
    auto issue = [&](int c) {
        int buf = c & 1;
        u32 boA = (u32)(buf * ABUF * 2);
        u32 boB = (u32)(buf * BBUF * 2);
        int Acol, Bcol;
        bool isQm;
        if (c < 60) {
            int p = c / 20, cc = c - p * 20;
            isQm = true;
            Acol = ((p == 2) ? 640 : 0) + cc * 32;
            Bcol = ((p == 1) ? 640 : 0) + cc * 32;
        } else {
            int c2 = c - 60;
            int p = c2 / 10, cc = c2 - p * 10;
            isQm = false;
            Acol = ((p == 2) ? 320 : 0) + cc * 32;
            Bcol = ((p == 1) ? 960 : 320) + cc * 32;
        }
        if (isQm) {
            cpasync16(dstA0 + boA, g_Aqm + offQm0 + Acol);
            cpasync16(dstA1 + boA, g_Aqm + offQm1 + Acol);
        } else {
            cpasync16(dstA0 + boA, g_At + offT0 + Acol);
            cpasync16(dstA1 + boA, g_At + offT1 + Acol);
        }
        cpasync16(dstB + boB, g_Bx + offB + Bcol);
        CP_COMMIT();
    };

    issue(0);

    for (int c = 0; c < 90; c++) {
        CP_WAIT0();
        __syncthreads();
        if (c + 1 < 90) issue(c + 1);

        const int buf = c & 1;
        const u32 aoff = (u32)(buf * ABUF * 2);
        const u32 boff = (u32)(buf * BBUF * 2);
        const bool isQ = (c < 60);
#pragma unroll
        for (int ks = 0; ks < 2; ks++) {
            const u32 kb = (u32)(ks * 32);   // 16 bf16 = 32 bytes
            u32 af0[4], af1[4], bf0[4], bf1[4];
            ldsm4(af0, aAddr[0] + aoff + kb);
            ldsm4(af1, aAddr[1] + aoff + kb);
            ldsm4(bf0, bAddr[0] + boff + kb);
            ldsm4(bf1, bAddr[1] + boff + kb);
            if (isQ) {
                mma16816(accQ[0][0], af0, &bf0[0]);
                mma16816(accQ[0][1], af0, &bf0[2]);
                mma16816(accQ[0][2], af0, &bf1[0]);
                mma16816(accQ[0][3], af0, &bf1[2]);
                mma16816(accQ[1][0], af1, &bf0[0]);
                mma16816(accQ[1][1], af1, &bf0[2]);
                mma16816(accQ[1][2], af1, &bf1[0]);
                mma16816(accQ[1][3], af1, &bf1[2]);
            } else {
                mma16816(accT[0][0], af0, &bf0[0]);
                mma16816(accT[0][1], af0, &bf0[2]);
                mma16816(accT[0][2], af0, &bf1[0]);
                mma16816(accT[0][3], af0, &bf1[2]);
                mma16816(accT[1][0], af1, &bf0[0]);
                mma16816(accT[1][1], af1, &bf0[2]);
                mma16816(accT[1][2], af1, &bf1[0]);
                mma16816(accT[1][3], af1, &bf1[2]);
            }
        }
    }

    // epilogue: fragment (mf,nf) element e: rows k = base+g (e0,e1) / base+g+8 (e2,e3),
    // cols v = nf*8 + 2t (+0/+1)
#pragma unroll
    for (int mf = 0; mf < 2; mf++) {
        int k_lo = k0 + warp_m * 32 + mf * 16 + g;
        int k_hi = k_lo + 8;
        float c1l = 0.f, c2l = 0.f, cil = 0.f, ckl = 0.f;
        float c1h = 0.f, c2h = 0.f, cih = 0.f, ckh = 0.f;
        if (k_lo < K_N) { c1l = g_c1[k_lo]; c2l = g_c2[k_lo]; cil = g_capinv[k_lo]; ckl = g_constk[k_lo]; }
        if (k_hi < K_N) { c1h = g_c1[k_hi]; c2h = g_c2[k_hi]; cih = g_capinv[k_hi]; ckh = g_constk[k_hi]; }
#pragma unroll
        for (int nf = 0; nf < 4; nf++) {
            int v = v0 + warp_n * 32 + nf * 8 + 2 * t;
            if (v >= V_N) continue;
            if (k_lo < K_N) {
                float q0 = accQ[mf][nf][0] + c1l;
                float t0 = accT[mf][nf][0] - c2l;
                float q1 = accQ[mf][nf][1] + c1l;
                float t1 = accT[mf][nf][1] - c2l;
                float2 r;
                r.x = ckl - 0.5f * (q0 - t0 * t0 * cil);
                r.y = ckl - 0.5f * (q1 - t1 * t1 * cil);
                *reinterpret_cast<float2*>(&g_logp[(size_t)k_lo * V_N + v]) = r;
            }
            if (k_hi < K_N) {
                float q0 = accQ[mf][nf][2] + c1h;
                float t0 = accT[mf][nf][2] - c2h;
                float q1 = accQ[mf][nf][3] + c1h;
                float t1 = accT[mf][nf][3] - c2h;
                float2 r;
                r.x = ckh - 0.5f * (q0 - t0 * t0 * cih);
                r.y = ckh - 0.5f * (q1 - t1 * t1 * cih);
                *reinterpret_cast<float2*>(&g_logp[(size_t)k_hi * V_N + v]) = r;
            }
        }
    }
}

// ---------------- kernel 4a: per-(topic, chunk) partial max/sum ----------------
#define NCH 8
#define CHV (V_N / NCH)   // 12500

__global__ void softmax_partial() {
    const int k = blockIdx.x;
    const int c = blockIdx.y;
    const int tid = threadIdx.x;
    const float4* p = reinterpret_cast<const float4*>(&g_logp[(size_t)k * V_N + c * CHV]);
    const int n4 = CHV / 4;

    float m = -3.4e38f;
    for (int f = tid; f < n4; f += 256) {
        float4 x = p[f];
        m = fmaxf(m, fmaxf(fmaxf(x.x, x.y), fmaxf(x.z, x.w)));
    }
    __shared__ float red[256];
    red[tid] = m;
    __syncthreads();
    for (int off = 128; off > 0; off >>= 1) {
        if (tid < off) red[tid] = fmaxf(red[tid], red[tid + off]);
        __syncthreads();
    }
    float M = red[0];
    __syncthreads();

    float s = 0.f;
    for (int f = tid; f < n4; f += 256) {
        float4 x = p[f];
        s += __expf(x.x - M) + __expf(x.y - M) + __expf(x.z - M) + __expf(x.w - M);
    }
    red[tid] = s;
    __syncthreads();
    for (int off = 128; off > 0; off >>= 1) {
        if (tid < off) red[tid] += red[tid + off];
        __syncthreads();
    }
    if (tid == 0) {
        g_pmax[k * NCH + c] = M;
        g_psum[k * NCH + c] = red[0];
    }
}

// ---------------- kernel 4b: merge partials -> g_softc ----------------
__global__ void softmax_merge() {
    int k = blockIdx.x * blockDim.x + threadIdx.x;
    if (k < K_N) {
        float M = -3.4e38f;
#pragma unroll
        for (int c = 0; c < NCH; c++) M = fmaxf(M, g_pmax[k * NCH + c]);
        float S = 0.f;
#pragma unroll
        for (int c = 0; c < NCH; c++)
            S += g_psum[k * NCH + c] * __expf(g_pmax[k * NCH + c] - M);
        g_softc[k] = M + logf(S);
    }
}

// ---------------- kernel 5: word_dist = sx @ softmax(logp), f32x2 over v ----------------
#define VT 64
#define BT 64
#define KC 8

__global__ __launch_bounds__(256) void out_gemm(float* __restrict__ out) {
    __shared__ float wt [KC][VT];
    __shared__ float sxs[KC][BT];

    const int b0 = blockIdx.x * BT;   // b fastest -> logp tile L2 reuse
    const int v0 = blockIdx.y * VT;
    const int tid = threadIdx.x;
    const int tv = tid & 15;
    const int tb = tid >> 4;

    u64 acc[4][2];
#pragma unroll
    for (int a = 0; a < 4; a++) { acc[a][0] = 0ull; acc[a][1] = 0ull; }

    for (int kc = 0; kc < K_N; kc += KC) {
        __syncthreads();
#pragma unroll
        for (int r = 0; r < 2; r++) {
            int e = tid + r * 256;
            int kk = e >> 6, vv = e & 63;
            int k = kc + kk;
            int v = v0 + vv;
            float x = (v < V_N) ? g_logp[(size_t)k * V_N + v] : -3.0e38f;
            wt[kk][vv] = __expf(x - g_softc[k]);
        }
#pragma unroll
        for (int r = 0; r < 2; r++) {
            int e = tid + r * 256;
            int kk = e >> 6, bb = e & 63;
            sxs[kk][bb] = g_sxT[(kc + kk) * B_N + b0 + bb];
        }
        __syncthreads();
#pragma unroll
        for (int kk = 0; kk < KC; kk++) {
            const u64* ap = reinterpret_cast<const u64*>(&wt[kk][tv * 4]);
            u64 a0 = ap[0], a1 = ap[1];
            float4 s4 = *reinterpret_cast<const float4*>(&sxs[kk][tb * 4]);
            u64 sd0 = pack2(s4.x, s4.x);
            u64 sd1 = pack2(s4.y, s4.y);
            u64 sd2 = pack2(s4.z, s4.z);
            u64 sd3 = pack2(s4.w, s4.w);
            acc[0][0] = fma2(sd0, a0, acc[0][0]); acc[0][1] = fma2(sd0, a1, acc[0][1]);
            acc[1][0] = fma2(sd1, a0, acc[1][0]); acc[1][1] = fma2(sd1, a1, acc[1][1]);
            acc[2][0] = fma2(sd2, a0, acc[2][0]); acc[2][1] = fma2(sd2, a1, acc[2][1]);
            acc[3][0] = fma2(sd3, a0, acc[3][0]); acc[3][1] = fma2(sd3, a1, acc[3][1]);
        }
    }

    const int vw = v0 + tv * 4;
    if (vw < V_N) {
#pragma unroll
        for (int jb = 0; jb < 4; jb++) {
            int b = b0 + tb * 4 + jb;
            float r0, r1, r2, r3;
            unpack2(acc[jb][0], r0, r1);
            unpack2(acc[jb][1], r2, r3);
            *reinterpret_cast<float4*>(&out[(size_t)b * OUTSTRIDE + K_N + vw]) =
                make_float4(r0, r1, r2, r3);
        }
    }
}

// ---------------- launch ----------------
extern "C" void kernel_launch(void* const* d_in, const int* in_sizes, int n_in,
                              void* d_out, int out_size) {
    const float* sx = (const float*)d_in[0];   // (256, 200)
    const float* wv = (const float*)d_in[1];   // (100000, 300)
    const float* mu = (const float*)d_in[2];   // (200, 300)
    const float* cf = (const float*)d_in[3];   // (200, 300)
    const float* cd = (const float*)d_in[4];   // (200, 300)
    float* out = (float*)d_out;                // (256, 100200)

    topic_prep<<<K_N, 128>>>(mu, cf, cd);
    wsplit<<<(V_N * 40 + 255) / 256, 256>>>(wv);
    sx_prep<<<(B_N * K_N + 255) / 256, 256>>>(sx, out);
    logp_mma<<<dim3(2, VTILES), 256>>>();
    softmax_partial<<<dim3(K_N, NCH), 256>>>();
    softmax_merge<<<1, 256>>>();
    out_gemm<<<dim3(B_N / BT, (V_N + VT - 1) / VT), 256>>>(out);
}